// round 15
// baseline (speedup 1.0000x reference)
#include <cuda_runtime.h>
#include <cuda_bf16.h>
#include <cstdint>

#define NN 128
#define LL 512
#define HIDDEN 512
#define EMBED 256
#define GCTAS 128
#define TTHR 512

// ===== Kernel 3 (recurrent) smem layout =====
// W-hi rows n=0..63 (n = hc_local*4+gate), k=0..511, stride 1040B (65ch, 65%8=1)
#define WSTR2 1040
#define SM_WH2 0
#define SM_WL2 66560         // 64*1040
#define SM_R   133120        // A ring: 4 bufs x 8KB (XOR-swizzled)
#define ABUF   8192
#define ASPL   4096
#define SM_TOT3 165888       // 133120 + 32768

// ===== Kernel 2 (precompute) smem layout =====
#define PSTR 528             // 33ch, 33%8=1 -> conflict-free ldmatrix
#define PW_H 0               // 64*528 = 33792
#define PW_L 33792
#define PA_H 67584           // 128*528 = 67584
#define PA_L 135168
#define PSM_TOT 202752

__device__ __nv_bfloat16 g_hh[2][NN * HIDDEN];
__device__ __nv_bfloat16 g_hl[2][NN * HIDDEN];
__device__ __nv_bfloat16 g_xh[LL][NN * EMBED];
__device__ __nv_bfloat16 g_xl[LL][NN * EMBED];
__device__ float g_Dx[LL][NN * 2048];           // x-part gate pre-activations (+bias)
__device__ unsigned g_ecnt;
__device__ volatile unsigned g_egen;
__device__ unsigned g_cntM[4 * 32];
__device__ volatile unsigned g_genM[4 * 32];

__device__ __forceinline__ uint32_t smem_u32(const void* p) {
    uint32_t a;
    asm("{ .reg .u64 t; cvta.to.shared.u64 t, %1; cvt.u32.u64 %0, t; }" : "=r"(a) : "l"(p));
    return a;
}
__device__ __forceinline__ float sigf(float x) {
    return __fdividef(1.0f, 1.0f + __expf(-x));
}
__device__ __forceinline__ float tanhf_fast(float x) {
    return __fdividef(2.0f, 1.0f + __expf(-2.0f * x)) - 1.0f;
}

#define LDSM4(r0, r1, r2, r3, ad)                                                \
    asm volatile("ldmatrix.sync.aligned.m8n8.x4.shared.b16 {%0,%1,%2,%3}, [%4];" \
                 : "=r"(r0), "=r"(r1), "=r"(r2), "=r"(r3) : "r"(ad))

__device__ __forceinline__ void mma16816(float* d, uint32_t a0, uint32_t a1,
                                         uint32_t a2, uint32_t a3, uint32_t b0,
                                         uint32_t b1) {
    asm volatile(
        "mma.sync.aligned.m16n8k16.row.col.f32.bf16.bf16.f32 "
        "{%0,%1,%2,%3},{%4,%5,%6,%7},{%8,%9},{%0,%1,%2,%3};"
        : "+f"(d[0]), "+f"(d[1]), "+f"(d[2]), "+f"(d[3])
        : "r"(a0), "r"(a1), "r"(a2), "r"(a3), "r"(b0), "r"(b1));
}

// ============ Kernel 1: embed gather -> bf16 hi/lo ============
__global__ void embed_kernel(const int* __restrict__ X, const float* __restrict__ E) {
    __shared__ int toks[NN];
    const int t = blockIdx.x;
    const int tid = threadIdx.x;
    if (tid < NN) toks[tid] = X[tid * LL + t];
    __syncthreads();
    __nv_bfloat16* dh = g_xh[t];
    __nv_bfloat16* dl = g_xl[t];
    for (int i = tid; i < NN * EMBED; i += 256) {
        float v = E[(size_t)toks[i >> 8] * EMBED + (i & 255)];
        __nv_bfloat16 hi = __float2bfloat16(v);
        dh[i] = hi;
        dl[i] = __float2bfloat16(v - __bfloat162float(hi));
    }
}

// ============ Kernel 2: x-GEMM precompute ============
// grid (32 colgrp, 32 tgrp), 512 thr. CTA: M=128, N=64 gate-cols, K=256 (x), 16 t.
extern __shared__ char psm[];
__global__ void __launch_bounds__(512, 1)
precomp_kernel(const float* __restrict__ Wi, const float* __restrict__ bi,
               const float* __restrict__ Wf, const float* __restrict__ bf,
               const float* __restrict__ Wo, const float* __restrict__ bo,
               const float* __restrict__ Wh, const float* __restrict__ bh) {
    __shared__ float s_bias[64];
    const int tid = threadIdx.x;
    const int warp = tid >> 5;
    const int lane = tid & 31;
    const int mq = warp >> 2;
    const int nq = warp & 3;
    const int colgrp = blockIdx.x;
    const int tgrp = blockIdx.y;
    const uint32_t su = smem_u32(psm);

    // W-x slice (k = 512 + j, j 0..255), rows n = hc_local*4+gate
    for (int n = 0; n < 64; n++) {
        int hc = colgrp * 16 + (n >> 2), gate = n & 3;
        const float* Wg = (gate == 0) ? Wi : (gate == 1) ? Wf : (gate == 2) ? Wo : Wh;
        for (int j = tid; j < 256; j += 512) {
            float w = Wg[(512 + j) * HIDDEN + hc];
            __nv_bfloat16 hi = __float2bfloat16(w);
            *(__nv_bfloat16*)(psm + PW_H + n * PSTR + j * 2) = hi;
            *(__nv_bfloat16*)(psm + PW_L + n * PSTR + j * 2) =
                __float2bfloat16(w - __bfloat162float(hi));
        }
    }
    if (tid < 64) {
        int gate = tid & 3;
        const float* Bg = (gate == 0) ? bi : (gate == 1) ? bf : (gate == 2) ? bo : bh;
        s_bias[tid] = Bg[colgrp * 16 + (tid >> 2)];
    }

    const uint32_t a_off = (uint32_t)((lane & 15) * PSTR + (lane >> 4) * 16);
    const uint32_t bW_off =
        (uint32_t)((nq * 16 + (lane >> 4) * 8 + (lane & 7)) * PSTR +
                   ((lane >> 3) & 1) * 16);
    const uint32_t bWh = su + PW_H + bW_off;
    const uint32_t bWl = su + PW_L + bW_off;

    float b00 = s_bias[nq * 16 + 0 + (lane & 3) * 2];   // loaded after sync below
    (void)b00;

    for (int tt = 0; tt < 16; tt++) {
        const int t = tgrp * 16 + tt;
        __syncthreads();   // prev iter's A reads done
        // stage A hi/lo: 128 rows x 512B each, dst stride 528
        {
            const char* srch = (const char*)g_xh[t];
            const char* srcl = (const char*)g_xl[t];
            for (int u = tid; u < 8192; u += 512) {
                int split = u >> 12, v = u & 4095, row = v >> 5, ch = v & 31;
                const char* s = (split ? srcl : srch) + row * 512 + ch * 16;
                uint32_t d = su + (split ? PA_L : PA_H) +
                             (uint32_t)(row * PSTR + ch * 16);
                asm volatile("cp.async.cg.shared.global [%0], [%1], 16;" ::"r"(d),
                             "l"(s));
            }
            asm volatile("cp.async.commit_group;" ::: "memory");
            asm volatile("cp.async.wait_group 0;" ::: "memory");
            __syncthreads();
        }

        float D0[2][2][4], D1a[2][2][4], D1b[2][2][4];
#pragma unroll
        for (int a = 0; a < 2; a++)
#pragma unroll
            for (int b = 0; b < 2; b++)
#pragma unroll
                for (int d = 0; d < 4; d++) {
                    D0[a][b][d] = 0.0f;
                    D1a[a][b][d] = 0.0f;
                    D1b[a][b][d] = 0.0f;
                }

#pragma unroll 4
        for (int kg = 0; kg < 16; kg++) {
            const uint32_t kb = (uint32_t)(kg * 32);
            uint32_t bh0, bh1, bh2, bh3, bl0, bl1, bl2, bl3;
            LDSM4(bh0, bh1, bh2, bh3, bWh + kb);
            LDSM4(bl0, bl1, bl2, bl3, bWl + kb);
#pragma unroll
            for (int mt = 0; mt < 2; mt++) {
                uint32_t ab = su + PA_H + (uint32_t)((mq * 32 + mt * 16) * PSTR) +
                              a_off + kb;
                uint32_t h0, h1, h2, h3, l0, l1, l2, l3;
                LDSM4(h0, h1, h2, h3, ab);
                LDSM4(l0, l1, l2, l3, ab + (PA_L - PA_H));
                mma16816(D0[mt][0], h0, h1, h2, h3, bh0, bh1);
                mma16816(D0[mt][1], h0, h1, h2, h3, bh2, bh3);
                mma16816(D1a[mt][0], l0, l1, l2, l3, bh0, bh1);
                mma16816(D1a[mt][1], l0, l1, l2, l3, bh2, bh3);
                mma16816(D1b[mt][0], h0, h1, h2, h3, bl0, bl1);
                mma16816(D1b[mt][1], h0, h1, h2, h3, bl2, bl3);
            }
        }

        // write D_x (+bias), fragment mapping of m16n8k16
        float* dxt = g_Dx[t];
#pragma unroll
        for (int mt = 0; mt < 2; mt++)
#pragma unroll
            for (int nf = 0; nf < 2; nf++) {
                int nl = nq * 16 + nf * 8 + (lane & 3) * 2;
                float bv0 = s_bias[nl], bv1 = s_bias[nl + 1];
                int ncol = colgrp * 64 + nl;
                int r0 = mq * 32 + mt * 16 + (lane >> 2);
                float s0 = D0[mt][nf][0] + D1a[mt][nf][0] + D1b[mt][nf][0] + bv0;
                float s1 = D0[mt][nf][1] + D1a[mt][nf][1] + D1b[mt][nf][1] + bv1;
                float s2 = D0[mt][nf][2] + D1a[mt][nf][2] + D1b[mt][nf][2] + bv0;
                float s3 = D0[mt][nf][3] + D1a[mt][nf][3] + D1b[mt][nf][3] + bv1;
                *(float2*)(dxt + r0 * 2048 + ncol) = make_float2(s0, s1);
                *(float2*)(dxt + (r0 + 8) * 2048 + ncol) = make_float2(s2, s3);
            }
    }
}

// ============ Kernel 3: recurrent h-GEMM loop ============
__device__ __forceinline__ void entrybarrier() {
    __syncthreads();
    if (threadIdx.x == 0) {
        unsigned my = g_egen;
        __threadfence();
        unsigned old = atomicAdd(&g_ecnt, 1u);
        if (old == (GCTAS - 1)) {
            atomicExch(&g_ecnt, 0u);
            __threadfence();
            g_egen = my + 1u;
        } else {
            while (g_egen == my) { __nanosleep(64); }
        }
        __threadfence();
    }
    __syncthreads();
}

// stage a PAIR of h k64 tiles (T, T+1) -> bufs T%4, (T+1)%4
__device__ __forceinline__ void stage_pair(int tid, uint32_t su, int T,
                                           const char* ah, const char* al) {
    const int split = tid >> 8, row = (tid >> 3) & 31, ch = tid & 7;
    const uint32_t off =
        (uint32_t)(split * ASPL + row * 128 + ((ch ^ (row & 7)) << 4));
    const char* s0 = (split ? al : ah) + row * 1024 + T * 128 + ch * 16;
    const char* s1 = s0 + 128;
    uint32_t d0 = su + SM_R + (uint32_t)((T & 3) * ABUF) + off;
    uint32_t d1 = su + SM_R + (uint32_t)(((T + 1) & 3) * ABUF) + off;
    asm volatile("cp.async.cg.shared.global [%0], [%1], 16;" ::"r"(d0), "l"(s0));
    asm volatile("cp.async.cg.shared.global [%0], [%1], 16;" ::"r"(d1), "l"(s1));
    asm volatile("cp.async.commit_group;" ::: "memory");
}

extern __shared__ char smem_raw[];

__global__ void __launch_bounds__(TTHR, 1)
lstm_hmma(const float* __restrict__ Wi, const float* __restrict__ Wf,
          const float* __restrict__ Wo, const float* __restrict__ Wh,
          float* __restrict__ out) {
    const int tid = threadIdx.x;
    const int warp = tid >> 5;
    const int lane = tid & 31;
    const int kq = warp >> 2;
    const int nq = warp & 3;
    const uint32_t su = smem_u32(smem_raw);
    char* dyn = smem_raw;
    float* red = (float*)(smem_raw + SM_R);

    const int mslice = blockIdx.x & 3;
    const int colgrp = blockIdx.x >> 2;
    const int mbase = mslice * 32;
    const int colbase = colgrp * 16;

    if (blockIdx.x == 0 && tid < 4) {
        g_cntM[tid * 32] = 0u;
        g_genM[tid * 32] = 0u;
    }

    // W-h resident (k = 0..511), rows n = hc_local*4 + gate
    for (int n = 0; n < 64; n++) {
        int hc = colbase + (n >> 2), gate = n & 3;
        const float* Wg = (gate == 0) ? Wi : (gate == 1) ? Wf : (gate == 2) ? Wo : Wh;
        for (int j = tid; j < 512; j += TTHR) {
            float w = Wg[j * HIDDEN + hc];
            __nv_bfloat16 hi = __float2bfloat16(w);
            *(__nv_bfloat16*)(dyn + SM_WH2 + n * WSTR2 + j * 2) = hi;
            *(__nv_bfloat16*)(dyn + SM_WL2 + n * WSTR2 + j * 2) =
                __float2bfloat16(w - __bfloat162float(hi));
        }
    }
    if (tid < 256) {
        ((unsigned*)g_hh[0])[blockIdx.x * 256 + tid] = 0u;
        ((unsigned*)g_hl[0])[blockIdx.x * 256 + tid] = 0u;
    }

    const int row16 = lane & 15, c0 = lane >> 4, r7 = row16 & 7;
    const uint32_t arow = (uint32_t)(row16 * 128);
    const uint32_t bW_off =
        (uint32_t)((nq * 16 + (lane >> 4) * 8 + (lane & 7)) * WSTR2 +
                   ((lane >> 3) & 1) * 16);
    const uint32_t bWh = su + SM_WH2 + bW_off;
    const uint32_t bWl = su + SM_WL2 + bW_off;

    const int tsel = kq >> 1;
    const int kk0 = (kq & 1) * 2;

    const int me = tid >> 4;
    const int hce = tid & 15;
    int bidx[4];
#pragma unroll
    for (int g = 0; g < 4; g++) {
        int n = hce * 4 + g;
        int nqr = n >> 4, nt = (n >> 3) & 1, nc = n & 7;
        int mt = me >> 4, mr = me & 15;
        int lane_r = (mr & 7) * 4 + (nc >> 1);
        int d = (mr >> 3) * 2 + (nc & 1);
        int f = mt * 8 + nt * 4 + d;
        bidx[g] = nqr * 512 + f * 32 + lane_r;
    }
    const float* pdx = g_Dx[0] + (mbase + me) * 2048 + colgrp * 64 + hce * 4;
    float cs = 0.0f;

    entrybarrier();   // h0 zero + counters visible

    for (int t = 0; t < LL; t++) {
        // prefetch D_x cell (independent of recurrence)
        const float4 dx = __ldg((const float4*)(pdx + (size_t)t * (NN * 2048)));

        // wait for h_{t-1} of our mslice
        if (warp == 0) {
            while (g_genM[mslice * 32] < (unsigned)t) { __nanosleep(64); }
        }
        __syncthreads();

        const int hp = t & 1;
        const char* ah = (const char*)g_hh[hp] + mbase * 1024;
        const char* al = (const char*)g_hl[hp] + mbase * 1024;
        stage_pair(tid, su, 0, ah, al);
        stage_pair(tid, su, 2, ah, al);

        float D0[2][2][4], D1a[2][2][4], D1b[2][2][4];
#pragma unroll
        for (int a = 0; a < 2; a++)
#pragma unroll
            for (int b = 0; b < 2; b++)
#pragma unroll
                for (int d = 0; d < 4; d++) {
                    D0[a][b][d] = 0.0f;
                    D1a[a][b][d] = 0.0f;
                    D1b[a][b][d] = 0.0f;
                }

#pragma unroll 1
        for (int w = 0; w < 4; w++) {
            if (w == 3)
                asm volatile("cp.async.wait_group 0;" ::: "memory");
            else
                asm volatile("cp.async.wait_group 1;" ::: "memory");
            __syncthreads();

            {
                const int myT = 2 * w + tsel;
                const uint32_t Ab = su + SM_R + (uint32_t)((myT & 3) * ABUF) + arow;
#pragma unroll
                for (int kx = 0; kx < 2; kx++) {
                    const int kk = kk0 + kx;
                    const uint32_t kb = (uint32_t)(myT * 128 + kk * 32);
                    uint32_t bh0, bh1, bh2, bh3, bl0, bl1, bl2, bl3;
                    LDSM4(bh0, bh1, bh2, bh3, bWh + kb);
                    LDSM4(bl0, bl1, bl2, bl3, bWl + kb);
                    const uint32_t sw = (uint32_t)(((kk * 2 + c0) ^ r7) << 4);
                    uint32_t ab = Ab + sw;
                    uint32_t h00, h01, h02, h03, h10, h11, h12, h13;
                    uint32_t l00, l01, l02, l03, l10, l11, l12, l13;
                    LDSM4(h00, h01, h02, h03, ab);
                    LDSM4(h10, h11, h12, h13, ab + 2048);
                    LDSM4(l00, l01, l02, l03, ab + ASPL);
                    LDSM4(l10, l11, l12, l13, ab + ASPL + 2048);
                    mma16816(D0[0][0], h00, h01, h02, h03, bh0, bh1);
                    mma16816(D0[0][1], h00, h01, h02, h03, bh2, bh3);
                    mma16816(D0[1][0], h10, h11, h12, h13, bh0, bh1);
                    mma16816(D0[1][1], h10, h11, h12, h13, bh2, bh3);
                    mma16816(D1a[0][0], l00, l01, l02, l03, bh0, bh1);
                    mma16816(D1a[0][1], l00, l01, l02, l03, bh2, bh3);
                    mma16816(D1a[1][0], l10, l11, l12, l13, bh0, bh1);
                    mma16816(D1a[1][1], l10, l11, l12, l13, bh2, bh3);
                    mma16816(D1b[0][0], h00, h01, h02, h03, bl0, bl1);
                    mma16816(D1b[0][1], h00, h01, h02, h03, bl2, bl3);
                    mma16816(D1b[1][0], h10, h11, h12, h13, bl0, bl1);
                    mma16816(D1b[1][1], h10, h11, h12, h13, bl2, bl3);
                }
            }

            if (w < 2) {
                __syncthreads();   // pair w fully read before overwriting its bufs
                stage_pair(tid, su, 2 * w + 4, ah, al);
            }
        }

        // merge chains
        float S[16];
#pragma unroll
        for (int a = 0; a < 2; a++)
#pragma unroll
            for (int b = 0; b < 2; b++)
#pragma unroll
                for (int d = 0; d < 4; d++)
                    S[a * 8 + b * 4 + d] =
                        D0[a][b][d] + D1a[a][b][d] + D1b[a][b][d];

        // single-phase cross-kq reduction over the drained ring
        __syncthreads();
        {
            int base = warp * 512 + lane;
#pragma unroll
            for (int f = 0; f < 16; f++) red[base + f * 32] = S[f];
        }
        __syncthreads();
        float a4[4];
#pragma unroll
        for (int g = 0; g < 4; g++)
            a4[g] = (red[bidx[g]] + red[bidx[g] + 2048]) +
                    (red[bidx[g] + 4096] + red[bidx[g] + 6144]);
        __syncthreads();   // ring free for next step's staging

        // gates (bias folded into D_x) + state update + publish
        const int pn = hp ^ 1;
        {
            float iv = sigf(a4[0] + dx.x);
            float fv = sigf(a4[1] + dx.y);
            float ov = sigf(a4[2] + dx.z);
            float gv = tanhf_fast(a4[3] + dx.w);
            cs = fv * cs + iv * gv;
            float hv = ov * tanhf_fast(cs);
            int mg = mbase + me, hcg = colbase + hce;
            __nv_bfloat16 hi = __float2bfloat16(hv);
            g_hh[pn][mg * HIDDEN + hcg] = hi;
            g_hl[pn][mg * HIDDEN + hcg] = __float2bfloat16(hv - __bfloat162float(hi));
            if (t == LL - 1) out[mg * HIDDEN + hcg] = hv;
        }

        __syncthreads();
        if (tid == 0) {
            __threadfence();
            unsigned old = atomicAdd(&g_cntM[mslice * 32], 1u);
            if ((old & 31u) == 31u) {
                __threadfence();
                g_genM[mslice * 32] = (unsigned)(t + 1);
            }
        }
    }
}

extern "C" void kernel_launch(void* const* d_in, const int* in_sizes, int n_in,
                              void* d_out, int out_size) {
    const int* X = (const int*)d_in[0];
    const float* E = (const float*)d_in[1];
    const float* Wi = (const float*)d_in[2];
    const float* bi = (const float*)d_in[3];
    const float* Wf = (const float*)d_in[4];
    const float* bf = (const float*)d_in[5];
    const float* Wo = (const float*)d_in[6];
    const float* bo = (const float*)d_in[7];
    const float* Wh = (const float*)d_in[8];
    const float* bh = (const float*)d_in[9];
    float* out = (float*)d_out;

    embed_kernel<<<LL, 256>>>(X, E);

    cudaFuncSetAttribute(precomp_kernel, cudaFuncAttributeMaxDynamicSharedMemorySize,
                         PSM_TOT);
    precomp_kernel<<<dim3(32, 32), 512, PSM_TOT>>>(Wi, bi, Wf, bf, Wo, bo, Wh, bh);

    cudaFuncSetAttribute(lstm_hmma, cudaFuncAttributeMaxDynamicSharedMemorySize,
                         SM_TOT3);
    lstm_hmma<<<GCTAS, TTHR, SM_TOT3>>>(Wi, Wf, Wo, Wh, out);
}

// round 16
// speedup vs baseline: 1.0958x; 1.0958x over previous
#include <cuda_runtime.h>
#include <cuda_bf16.h>
#include <cstdint>

#define NN 128
#define LL 512
#define HIDDEN 512
#define EMBED 256
#define GCTAS 128
#define TTHR 512

// ===== Kernel 3 (recurrent) smem =====
#define WSTR2 1040
#define SM_WH2 0
#define SM_WL2 66560         // 64*1040
#define SM_R   133120        // A ring: 8 bufs x 8KB
#define ABUF   8192
#define ASPL   4096
#define SM_TOT3 198656       // 133120 + 8*8192

// ===== Kernel 2 (precompute) smem =====
#define PSTR 528
#define PW_H 0
#define PW_L 33792
#define PA_H 67584
#define PA_L 135168
#define PSM_TOT 202752

__device__ __nv_bfloat16 g_hh[2][NN * HIDDEN];
__device__ __nv_bfloat16 g_hl[2][NN * HIDDEN];
__device__ __nv_bfloat16 g_xh[LL][NN * EMBED];
__device__ __nv_bfloat16 g_xl[LL][NN * EMBED];
__device__ float g_Dx[LL][NN * 2048];           // x gate pre-activations (+bias)
__device__ unsigned g_ecnt;
__device__ volatile unsigned g_egen;
__device__ volatile unsigned g_flag[128 * 8];   // [ (mslice*32+colgrp)*8 ] == t+1

__device__ __forceinline__ uint32_t smem_u32(const void* p) {
    uint32_t a;
    asm("{ .reg .u64 t; cvta.to.shared.u64 t, %1; cvt.u32.u64 %0, t; }" : "=r"(a) : "l"(p));
    return a;
}
__device__ __forceinline__ float sigf(float x) {
    return __fdividef(1.0f, 1.0f + __expf(-x));
}
__device__ __forceinline__ float tanhf_fast(float x) {
    return __fdividef(2.0f, 1.0f + __expf(-2.0f * x)) - 1.0f;
}

#define LDSM4(r0, r1, r2, r3, ad)                                                \
    asm volatile("ldmatrix.sync.aligned.m8n8.x4.shared.b16 {%0,%1,%2,%3}, [%4];" \
                 : "=r"(r0), "=r"(r1), "=r"(r2), "=r"(r3) : "r"(ad))

__device__ __forceinline__ void mma16816(float* d, uint32_t a0, uint32_t a1,
                                         uint32_t a2, uint32_t a3, uint32_t b0,
                                         uint32_t b1) {
    asm volatile(
        "mma.sync.aligned.m16n8k16.row.col.f32.bf16.bf16.f32 "
        "{%0,%1,%2,%3},{%4,%5,%6,%7},{%8,%9},{%0,%1,%2,%3};"
        : "+f"(d[0]), "+f"(d[1]), "+f"(d[2]), "+f"(d[3])
        : "r"(a0), "r"(a1), "r"(a2), "r"(a3), "r"(b0), "r"(b1));
}

// ============ Kernel 1: embed gather -> bf16 hi/lo ============
__global__ void embed_kernel(const int* __restrict__ X, const float* __restrict__ E) {
    __shared__ int toks[NN];
    const int t = blockIdx.x;
    const int tid = threadIdx.x;
    if (tid < NN) toks[tid] = X[tid * LL + t];
    __syncthreads();
    __nv_bfloat16* dh = g_xh[t];
    __nv_bfloat16* dl = g_xl[t];
    for (int i = tid; i < NN * EMBED; i += 256) {
        float v = E[(size_t)toks[i >> 8] * EMBED + (i & 255)];
        __nv_bfloat16 hi = __float2bfloat16(v);
        dh[i] = hi;
        dl[i] = __float2bfloat16(v - __bfloat162float(hi));
    }
}

// ============ Kernel 2: x-GEMM precompute (unchanged from R15, passed) ============
extern __shared__ char psm[];
__global__ void __launch_bounds__(512, 1)
precomp_kernel(const float* __restrict__ Wi, const float* __restrict__ bi,
               const float* __restrict__ Wf, const float* __restrict__ bf,
               const float* __restrict__ Wo, const float* __restrict__ bo,
               const float* __restrict__ Wh, const float* __restrict__ bh) {
    __shared__ float s_bias[64];
    const int tid = threadIdx.x;
    const int warp = tid >> 5;
    const int lane = tid & 31;
    const int mq = warp >> 2;
    const int nq = warp & 3;
    const int colgrp = blockIdx.x;
    const int tgrp = blockIdx.y;
    const uint32_t su = smem_u32(psm);

    for (int n = 0; n < 64; n++) {
        int hc = colgrp * 16 + (n >> 2), gate = n & 3;
        const float* Wg = (gate == 0) ? Wi : (gate == 1) ? Wf : (gate == 2) ? Wo : Wh;
        for (int j = tid; j < 256; j += 512) {
            float w = Wg[(512 + j) * HIDDEN + hc];
            __nv_bfloat16 hi = __float2bfloat16(w);
            *(__nv_bfloat16*)(psm + PW_H + n * PSTR + j * 2) = hi;
            *(__nv_bfloat16*)(psm + PW_L + n * PSTR + j * 2) =
                __float2bfloat16(w - __bfloat162float(hi));
        }
    }
    if (tid < 64) {
        int gate = tid & 3;
        const float* Bg = (gate == 0) ? bi : (gate == 1) ? bf : (gate == 2) ? bo : bh;
        s_bias[tid] = Bg[colgrp * 16 + (tid >> 2)];
    }

    const uint32_t a_off = (uint32_t)((lane & 15) * PSTR + (lane >> 4) * 16);
    const uint32_t bW_off =
        (uint32_t)((nq * 16 + (lane >> 4) * 8 + (lane & 7)) * PSTR +
                   ((lane >> 3) & 1) * 16);
    const uint32_t bWh = su + PW_H + bW_off;
    const uint32_t bWl = su + PW_L + bW_off;

    for (int tt = 0; tt < 16; tt++) {
        const int t = tgrp * 16 + tt;
        __syncthreads();
        {
            const char* srch = (const char*)g_xh[t];
            const char* srcl = (const char*)g_xl[t];
            for (int u = tid; u < 8192; u += 512) {
                int split = u >> 12, v = u & 4095, row = v >> 5, ch = v & 31;
                const char* s = (split ? srcl : srch) + row * 512 + ch * 16;
                uint32_t d = su + (split ? PA_L : PA_H) +
                             (uint32_t)(row * PSTR + ch * 16);
                asm volatile("cp.async.cg.shared.global [%0], [%1], 16;" ::"r"(d),
                             "l"(s));
            }
            asm volatile("cp.async.commit_group;" ::: "memory");
            asm volatile("cp.async.wait_group 0;" ::: "memory");
            __syncthreads();
        }

        float D0[2][2][4], D1a[2][2][4], D1b[2][2][4];
#pragma unroll
        for (int a = 0; a < 2; a++)
#pragma unroll
            for (int b = 0; b < 2; b++)
#pragma unroll
                for (int d = 0; d < 4; d++) {
                    D0[a][b][d] = 0.0f;
                    D1a[a][b][d] = 0.0f;
                    D1b[a][b][d] = 0.0f;
                }

#pragma unroll 4
        for (int kg = 0; kg < 16; kg++) {
            const uint32_t kb = (uint32_t)(kg * 32);
            uint32_t bh0, bh1, bh2, bh3, bl0, bl1, bl2, bl3;
            LDSM4(bh0, bh1, bh2, bh3, bWh + kb);
            LDSM4(bl0, bl1, bl2, bl3, bWl + kb);
#pragma unroll
            for (int mt = 0; mt < 2; mt++) {
                uint32_t ab = su + PA_H + (uint32_t)((mq * 32 + mt * 16) * PSTR) +
                              a_off + kb;
                uint32_t h0, h1, h2, h3, l0, l1, l2, l3;
                LDSM4(h0, h1, h2, h3, ab);
                LDSM4(l0, l1, l2, l3, ab + (PA_L - PA_H));
                mma16816(D0[mt][0], h0, h1, h2, h3, bh0, bh1);
                mma16816(D0[mt][1], h0, h1, h2, h3, bh2, bh3);
                mma16816(D1a[mt][0], l0, l1, l2, l3, bh0, bh1);
                mma16816(D1a[mt][1], l0, l1, l2, l3, bh2, bh3);
                mma16816(D1b[mt][0], h0, h1, h2, h3, bl0, bl1);
                mma16816(D1b[mt][1], h0, h1, h2, h3, bl2, bl3);
            }
        }

        float* dxt = g_Dx[t];
#pragma unroll
        for (int mt = 0; mt < 2; mt++)
#pragma unroll
            for (int nf = 0; nf < 2; nf++) {
                int nl = nq * 16 + nf * 8 + (lane & 3) * 2;
                float bv0 = s_bias[nl], bv1 = s_bias[nl + 1];
                int ncol = colgrp * 64 + nl;
                int r0 = mq * 32 + mt * 16 + (lane >> 2);
                float s0 = D0[mt][nf][0] + D1a[mt][nf][0] + D1b[mt][nf][0] + bv0;
                float s1 = D0[mt][nf][1] + D1a[mt][nf][1] + D1b[mt][nf][1] + bv1;
                float s2 = D0[mt][nf][2] + D1a[mt][nf][2] + D1b[mt][nf][2] + bv0;
                float s3 = D0[mt][nf][3] + D1a[mt][nf][3] + D1b[mt][nf][3] + bv1;
                *(float2*)(dxt + r0 * 2048 + ncol) = make_float2(s0, s1);
                *(float2*)(dxt + (r0 + 8) * 2048 + ncol) = make_float2(s2, s3);
            }
    }
}

// ============ Kernel 3: recurrent h-GEMM loop ============
__device__ __forceinline__ void entrybarrier() {
    __syncthreads();
    if (threadIdx.x == 0) {
        unsigned my = g_egen;
        __threadfence();
        unsigned old = atomicAdd(&g_ecnt, 1u);
        if (old == (GCTAS - 1)) {
            atomicExch(&g_ecnt, 0u);
            __threadfence();
            g_egen = my + 1u;
        } else {
            while (g_egen == my) { __nanosleep(64); }
        }
        __threadfence();
    }
    __syncthreads();
}

// stage a PAIR of h k64 tiles (T, T+1) -> bufs T, T+1 (8-buf ring, T<8)
__device__ __forceinline__ void stage_pair(int tid, uint32_t su, int T,
                                           const char* ah, const char* al) {
    const int split = tid >> 8, row = (tid >> 3) & 31, ch = tid & 7;
    const uint32_t off =
        (uint32_t)(split * ASPL + row * 128 + ((ch ^ (row & 7)) << 4));
    const char* s0 = (split ? al : ah) + row * 1024 + T * 128 + ch * 16;
    const char* s1 = s0 + 128;
    uint32_t d0 = su + SM_R + (uint32_t)(T * ABUF) + off;
    uint32_t d1 = su + SM_R + (uint32_t)((T + 1) * ABUF) + off;
    asm volatile("cp.async.cg.shared.global [%0], [%1], 16;" ::"r"(d0), "l"(s0));
    asm volatile("cp.async.cg.shared.global [%0], [%1], 16;" ::"r"(d1), "l"(s1));
    asm volatile("cp.async.commit_group;" ::: "memory");
}

extern __shared__ char smem_raw[];

#define COMPUTE_W(w_)                                                               \
    {                                                                               \
        const int myT = 2 * (w_) + tsel;                                            \
        const uint32_t Ab = su + SM_R + (uint32_t)(myT * ABUF) + arow;              \
        _Pragma("unroll")                                                           \
        for (int kx = 0; kx < 2; kx++) {                                            \
            const int kk = kk0 + kx;                                                \
            const uint32_t kb = (uint32_t)(myT * 128 + kk * 32);                    \
            uint32_t bh0, bh1, bh2, bh3, bl0, bl1, bl2, bl3;                        \
            LDSM4(bh0, bh1, bh2, bh3, bWh + kb);                                    \
            LDSM4(bl0, bl1, bl2, bl3, bWl + kb);                                    \
            const uint32_t sw = (uint32_t)(((kk * 2 + c0) ^ r7) << 4);              \
            uint32_t ab = Ab + sw;                                                  \
            uint32_t h00, h01, h02, h03, h10, h11, h12, h13;                        \
            uint32_t l00, l01, l02, l03, l10, l11, l12, l13;                        \
            LDSM4(h00, h01, h02, h03, ab);                                          \
            LDSM4(h10, h11, h12, h13, ab + 2048);                                   \
            LDSM4(l00, l01, l02, l03, ab + ASPL);                                   \
            LDSM4(l10, l11, l12, l13, ab + ASPL + 2048);                            \
            mma16816(D0[0][0], h00, h01, h02, h03, bh0, bh1);                       \
            mma16816(D0[0][1], h00, h01, h02, h03, bh2, bh3);                       \
            mma16816(D0[1][0], h10, h11, h12, h13, bh0, bh1);                       \
            mma16816(D0[1][1], h10, h11, h12, h13, bh2, bh3);                       \
            mma16816(D1a[0][0], l00, l01, l02, l03, bh0, bh1);                      \
            mma16816(D1a[0][1], l00, l01, l02, l03, bh2, bh3);                      \
            mma16816(D1a[1][0], l10, l11, l12, l13, bh0, bh1);                      \
            mma16816(D1a[1][1], l10, l11, l12, l13, bh2, bh3);                      \
            mma16816(D1b[0][0], h00, h01, h02, h03, bl0, bl1);                      \
            mma16816(D1b[0][1], h00, h01, h02, h03, bl2, bl3);                      \
            mma16816(D1b[1][0], h10, h11, h12, h13, bl0, bl1);                      \
            mma16816(D1b[1][1], h10, h11, h12, h13, bl2, bl3);                      \
        }                                                                           \
    }

#define WINDOW(w_, n_)                                              \
    asm volatile("cp.async.wait_group " #n_ ";" ::: "memory");      \
    __syncthreads();                                                \
    COMPUTE_W(w_)

__global__ void __launch_bounds__(TTHR, 1)
lstm_hmma(const float* __restrict__ Wi, const float* __restrict__ Wf,
          const float* __restrict__ Wo, const float* __restrict__ Wh,
          float* __restrict__ out) {
    const int tid = threadIdx.x;
    const int warp = tid >> 5;
    const int lane = tid & 31;
    const int kq = warp >> 2;
    const int nq = warp & 3;
    const uint32_t su = smem_u32(smem_raw);
    char* dyn = smem_raw;
    float* red = (float*)(smem_raw + SM_R);   // aliases bufs 0-3

    const int mslice = blockIdx.x & 3;
    const int colgrp = blockIdx.x >> 2;
    const int mbase = mslice * 32;
    const int colbase = colgrp * 16;

    if (blockIdx.x == 0 && tid < 128) g_flag[tid * 8] = 0u;

    // W-h resident (k = 0..511), rows n = hc_local*4 + gate
    for (int n = 0; n < 64; n++) {
        int hc = colbase + (n >> 2), gate = n & 3;
        const float* Wg = (gate == 0) ? Wi : (gate == 1) ? Wf : (gate == 2) ? Wo : Wh;
        for (int j = tid; j < 512; j += TTHR) {
            float w = Wg[j * HIDDEN + hc];
            __nv_bfloat16 hi = __float2bfloat16(w);
            *(__nv_bfloat16*)(dyn + SM_WH2 + n * WSTR2 + j * 2) = hi;
            *(__nv_bfloat16*)(dyn + SM_WL2 + n * WSTR2 + j * 2) =
                __float2bfloat16(w - __bfloat162float(hi));
        }
    }
    if (tid < 256) {
        ((unsigned*)g_hh[0])[blockIdx.x * 256 + tid] = 0u;
        ((unsigned*)g_hl[0])[blockIdx.x * 256 + tid] = 0u;
    }

    const int row16 = lane & 15, c0 = lane >> 4, r7 = row16 & 7;
    const uint32_t arow = (uint32_t)(row16 * 128);
    const uint32_t bW_off =
        (uint32_t)((nq * 16 + (lane >> 4) * 8 + (lane & 7)) * WSTR2 +
                   ((lane >> 3) & 1) * 16);
    const uint32_t bWh = su + SM_WH2 + bW_off;
    const uint32_t bWl = su + SM_WL2 + bW_off;

    const int tsel = kq >> 1;
    const int kk0 = (kq & 1) * 2;

    const int me = tid >> 4;
    const int hce = tid & 15;
    int bidx[4];
#pragma unroll
    for (int g = 0; g < 4; g++) {
        int n = hce * 4 + g;
        int nqr = n >> 4, nt = (n >> 3) & 1, nc = n & 7;
        int mt = me >> 4, mr = me & 15;
        int lane_r = (mr & 7) * 4 + (nc >> 1);
        int d = (mr >> 3) * 2 + (nc & 1);
        int f = mt * 8 + nt * 4 + d;
        bidx[g] = nqr * 512 + f * 32 + lane_r;
    }
    const float* pdx = g_Dx[0] + (mbase + me) * 2048 + colgrp * 64 + hce * 4;
    float cs = 0.0f;

    entrybarrier();   // h0 zero + flag resets visible

    // per-lane flag pointer (warp 0 poll): lane L watches colgrp L of our mslice
    const volatile unsigned* fpoll = &g_flag[(mslice * 32 + lane) * 8];

    for (int t = 0; t < LL; t++) {
        // prefetch D_x cell (independent of recurrence)
        const float4 dx = __ldg((const float4*)(pdx + (size_t)t * (NN * 2048)));

        // wait for h_{t-1} of our mslice: warp 0, one flag per lane
        if (warp == 0) {
            while (*fpoll < (unsigned)t) { __nanosleep(64); }
        }
        __syncthreads();

        const int hp = t & 1;
        const char* ah = (const char*)g_hh[hp] + mbase * 1024;
        const char* al = (const char*)g_hl[hp] + mbase * 1024;
        // stage all 8 h tiles (4 pairs, 4 commit groups) into bufs 0..7
        stage_pair(tid, su, 0, ah, al);
        stage_pair(tid, su, 2, ah, al);
        stage_pair(tid, su, 4, ah, al);
        stage_pair(tid, su, 6, ah, al);

        float D0[2][2][4], D1a[2][2][4], D1b[2][2][4];
#pragma unroll
        for (int a = 0; a < 2; a++)
#pragma unroll
            for (int b = 0; b < 2; b++)
#pragma unroll
                for (int d = 0; d < 4; d++) {
                    D0[a][b][d] = 0.0f;
                    D1a[a][b][d] = 0.0f;
                    D1b[a][b][d] = 0.0f;
                }

        WINDOW(0, 3)
        WINDOW(1, 2)
        WINDOW(2, 1)
        WINDOW(3, 0)

        // merge chains
        float S[16];
#pragma unroll
        for (int a = 0; a < 2; a++)
#pragma unroll
            for (int b = 0; b < 2; b++)
#pragma unroll
                for (int d = 0; d < 4; d++)
                    S[a * 8 + b * 4 + d] =
                        D0[a][b][d] + D1a[a][b][d] + D1b[a][b][d];

        // single-phase cross-kq reduction (aliases bufs 0-3; tiles 0-3 consumed)
        __syncthreads();
        {
            int base = warp * 512 + lane;
#pragma unroll
            for (int f = 0; f < 16; f++) red[base + f * 32] = S[f];
        }
        __syncthreads();
        float a4[4];
#pragma unroll
        for (int g = 0; g < 4; g++)
            a4[g] = (red[bidx[g]] + red[bidx[g] + 2048]) +
                    (red[bidx[g] + 4096] + red[bidx[g] + 6144]);

        // gates (bias folded into D_x) + state update
        const int pn = hp ^ 1;
        {
            float iv = sigf(a4[0] + dx.x);
            float fv = sigf(a4[1] + dx.y);
            float ov = sigf(a4[2] + dx.z);
            float gv = tanhf_fast(a4[3] + dx.w);
            cs = fv * cs + iv * gv;
            float hv = ov * tanhf_fast(cs);
            int mg = mbase + me, hcg = colbase + hce;
            __nv_bfloat16 hi = __float2bfloat16(hv);
            g_hh[pn][mg * HIDDEN + hcg] = hi;
            g_hl[pn][mg * HIDDEN + hcg] = __float2bfloat16(hv - __bfloat162float(hi));
            if (t == LL - 1) out[mg * HIDDEN + hcg] = hv;
        }

        // release publish: one STG, no atomics (also fences red reads vs next stage)
        __syncthreads();
        if (tid == 0) {
            __threadfence();
            g_flag[(mslice * 32 + colgrp) * 8] = (unsigned)(t + 1);
        }
    }
}

extern "C" void kernel_launch(void* const* d_in, const int* in_sizes, int n_in,
                              void* d_out, int out_size) {
    const int* X = (const int*)d_in[0];
    const float* E = (const float*)d_in[1];
    const float* Wi = (const float*)d_in[2];
    const float* bi = (const float*)d_in[3];
    const float* Wf = (const float*)d_in[4];
    const float* bf = (const float*)d_in[5];
    const float* Wo = (const float*)d_in[6];
    const float* bo = (const float*)d_in[7];
    const float* Wh = (const float*)d_in[8];
    const float* bh = (const float*)d_in[9];
    float* out = (float*)d_out;

    embed_kernel<<<LL, 256>>>(X, E);

    cudaFuncSetAttribute(precomp_kernel, cudaFuncAttributeMaxDynamicSharedMemorySize,
                         PSM_TOT);
    precomp_kernel<<<dim3(32, 32), 512, PSM_TOT>>>(Wi, bi, Wf, bf, Wo, bo, Wh, bh);

    cudaFuncSetAttribute(lstm_hmma, cudaFuncAttributeMaxDynamicSharedMemorySize,
                         SM_TOT3);
    lstm_hmma<<<GCTAS, TTHR, SM_TOT3>>>(Wi, Wf, Wo, Wh, out);
}